// round 15
// baseline (speedup 1.0000x reference)
#include <cuda_runtime.h>
#include <cuda_fp16.h>
#include <cuda_bf16.h>

// Problem constants (fixed by the reference setup_inputs)
#define BATCH 4
#define CH    256
#define HH    64
#define WW    64
#define NROI  256
#define PP    7        // pooled size == part size
#define SS    4        // samples per bin edge
#define SPATIAL_SCALE 0.125f
#define TRANS_STD     0.1f
#define NBINS (NROI * PP * PP)   // 12544
#define GRIDP 592                // 4 * 148: always fully resident at >=4 CTAs/SM
#define NTILES 4096              // transpose tiles: 2(w) * 8(c) * 256(b*h)
#define NWORK (NROI * PP)        // 1792 pool row-units

// 8 MB fp16 NHWC scratch: g_nhwc_h[((b*H + y)*W + x)*C + c]
__device__ __half g_nhwc_h[BATCH * HH * WW * CH];

// Per-bin precomputed geometry: 3 x float4 = 48B per bin.
//   [0] = wx[0..3]  [1] = wy[0..3]*inv (0 if count==0)  [2] = int4(xbase,ybase,b,-)
__device__ float4 g_bininfo[NBINS * 3];

// Monotonic barrier counter (replay-safe: never reset; target derived from ticket).
__device__ unsigned g_bar;

// ---------------------------------------------------------------------------
// Per-bin separable bilinear weights (one thread per bin).
// ---------------------------------------------------------------------------
__device__ __forceinline__ void compute_bin_info(
    int bin, const float* __restrict__ rois, const float* __restrict__ offset)
{
    const int n  = bin / (PP * PP);
    const int r  = bin % (PP * PP);
    const int ph = r / PP;
    const int pw = r % PP;

    const float* roi = rois + n * 5;
    const int   b      = (int)roi[0];
    const float roi_sw = rintf(roi[1]) * SPATIAL_SCALE - 0.5f;
    const float roi_sh = rintf(roi[2]) * SPATIAL_SCALE - 0.5f;
    const float roi_ew = (rintf(roi[3]) + 1.0f) * SPATIAL_SCALE - 0.5f;
    const float roi_eh = (rintf(roi[4]) + 1.0f) * SPATIAL_SCALE - 0.5f;
    const float roi_w  = fmaxf(roi_ew - roi_sw, 0.1f);
    const float roi_h  = fmaxf(roi_eh - roi_sh, 0.1f);
    const float bin_w  = roi_w / (float)PP;
    const float bin_h  = roi_h / (float)PP;
    const float sub_w  = bin_w / (float)SS;
    const float sub_h  = bin_h / (float)SS;

    const float tx_off = offset[(n * 2 + 0) * (PP * PP) + r] * TRANS_STD;
    const float ty_off = offset[(n * 2 + 1) * (PP * PP) + r] * TRANS_STD;

    const float wstart = (float)pw * bin_w + roi_sw + tx_off * roi_w;
    const float hstart = (float)ph * bin_h + roi_sh + ty_off * roi_h;

    float lwx[4] = {0.f, 0.f, 0.f, 0.f};
    int cw = 0, xb = 0;
    bool xset = false;
    #pragma unroll
    for (int s = 0; s < SS; s++) {
        const float wcoord = wstart + (float)s * sub_w;
        if (wcoord > -0.5f && wcoord < (float)WW - 0.5f) {
            cw++;
            const float wc = fminf(fmaxf(wcoord, 0.0f), (float)(WW - 1));
            const int x0 = (int)floorf(wc);
            if (!xset) { xb = x0; xset = true; }
            const float dx = wc - (float)x0;
            const int o0 = x0 - xb;
            const int o1 = min(x0 + 1, WW - 1) - xb;
            #pragma unroll
            for (int k = 0; k < 4; k++)
                lwx[k] += (o0 == k ? 1.0f - dx : 0.0f) + (o1 == k ? dx : 0.0f);
        }
    }
    float lwy[4] = {0.f, 0.f, 0.f, 0.f};
    int chh = 0, yb = 0;
    bool yset = false;
    #pragma unroll
    for (int s = 0; s < SS; s++) {
        const float hcoord = hstart + (float)s * sub_h;
        if (hcoord > -0.5f && hcoord < (float)HH - 0.5f) {
            chh++;
            const float hc = fminf(fmaxf(hcoord, 0.0f), (float)(HH - 1));
            const int y0 = (int)floorf(hc);
            if (!yset) { yb = y0; yset = true; }
            const float dy = hc - (float)y0;
            const int o0 = y0 - yb;
            const int o1 = min(y0 + 1, HH - 1) - yb;
            #pragma unroll
            for (int k = 0; k < 4; k++)
                lwy[k] += (o0 == k ? 1.0f - dy : 0.0f) + (o1 == k ? dy : 0.0f);
        }
    }

    const int cnt = cw * chh;
    const float inv = (cnt > 0) ? (1.0f / (float)cnt) : 0.0f;
    float4* bi = g_bininfo + bin * 3;
    bi[0] = make_float4(lwx[0], lwx[1], lwx[2], lwx[3]);
    bi[1] = make_float4(lwy[0] * inv, lwy[1] * inv, lwy[2] * inv, lwy[3] * inv);
    int4 ib = make_int4(xb, yb, b, 0);
    bi[2] = *reinterpret_cast<float4*>(&ib);
}

// ---------------------------------------------------------------------------
// Persistent fused kernel: phase 1 (bininfo + NCHW->NHWC fp16 transpose),
// device-wide barrier, phase 2 (gather+FMA pool).
// grid = 592 CTAs x 224 threads; regs capped <= 56 => 5 CTAs/SM => all resident.
// ---------------------------------------------------------------------------
__global__ __launch_bounds__(224, 5) void deform_roi_pool_fused(
    const float* __restrict__ data,
    const float* __restrict__ rois,
    const float* __restrict__ offset,
    float* __restrict__ out)
{
    __shared__ union {
        float  tile[32][33];     // phase 1 transpose staging
        float4 sm4[PP * 64];     // phase 2 result staging
    } smem;

    const int tid = threadIdx.x;

    // ======================= Phase 1a: bin-info ============================
    {
        const int bin = blockIdx.x * 224 + tid;    // 592*224 = 132608 >= NBINS
        if (bin < NBINS) compute_bin_info(bin, rois, offset);
    }

    // ======================= Phase 1b: transpose ===========================
    for (int t = blockIdx.x; t < NTILES; t += GRIDP) {
        const int cx = t & 1;              // w block   (0..1)
        const int cy = (t >> 1) & 7;       // c block   (0..7)
        const int bh = t >> 4;             // b*64 + h  (0..255)
        const int b  = bh >> 6;
        const int h  = bh & 63;
        const int c0 = cy * 32;
        const int w0 = cx * 32;

        __syncthreads();   // protect smem reuse from previous iteration
        for (int idx = tid; idx < 1024; idx += 224) {
            const int ci = idx >> 5;
            const int wi = idx & 31;
            smem.tile[ci][wi] = data[((b * CH + c0 + ci) * HH + h) * WW + w0 + wi];
        }
        __syncthreads();
        for (int idx = tid; idx < 512; idx += 224) {
            const int row = idx >> 4;      // w offset 0..31
            const int m   = idx & 15;      // half2 index within 32 channels
            const __half2 v = __floats2half2_rn(smem.tile[2 * m][row],
                                                smem.tile[2 * m + 1][row]);
            *reinterpret_cast<__half2*>(
                &g_nhwc_h[((size_t)(b * HH + h) * WW + (w0 + row)) * CH + c0 + 2 * m]) = v;
        }
    }

    // ======================= Device-wide barrier ===========================
    __syncthreads();
    if (tid == 0) {
        __threadfence();                               // publish phase-1 writes
        const unsigned ticket = atomicAdd(&g_bar, 1);
        const unsigned target = (ticket / GRIDP + 1u) * GRIDP;
        while (*(volatile unsigned*)&g_bar < target) {
            __nanosleep(64);
        }
        __threadfence();                               // acquire phase-1 writes
    }
    __syncthreads();

    // ======================= Phase 2: pool =================================
    for (int wb = blockIdx.x; wb < NWORK; wb += GRIDP) {
        const int n  = wb / 7;
        const int ph = wb % 7;
        const int group = tid >> 5;        // pw, 0..6
        const int c8    = tid & 31;        // lane: channels 8*c8 .. 8*c8+7
        const int bin   = n * (PP * PP) + ph * PP + group;

        // broadcast-load bin info (3 x LDG.128)
        const float4* __restrict__ bip = g_bininfo + bin * 3;
        const float4 fwx = __ldg(bip + 0);
        const float4 fwy = __ldg(bip + 1);             // includes 1/count
        const float4 fib = __ldg(bip + 2);
        const int4   ib  = *reinterpret_cast<const int4*>(&fib);
        const int xbase = ib.x, ybase = ib.y, b = ib.z;
        const float wx[4] = {fwx.x, fwx.y, fwx.z, fwx.w};
        const float wy[4] = {fwy.x, fwy.y, fwy.z, fwy.w};

        // gather + FMA: fp16 cell = 512B = 32 uint4, lane c8 reads uint4 #c8
        const uint4* __restrict__ base =
            reinterpret_cast<const uint4*>(g_nhwc_h)
            + (size_t)b * (HH * WW * 32) + c8;

        int xo[4];
        #pragma unroll
        for (int xi = 0; xi < 4; xi++)
            xo[xi] = min(xbase + xi, WW - 1) * 32;

        float4 acc0 = make_float4(0.f, 0.f, 0.f, 0.f);
        float4 acc1 = make_float4(0.f, 0.f, 0.f, 0.f);
        #pragma unroll
        for (int yi = 0; yi < 4; yi++) {
            const float wyv = wy[yi];
            if (wyv == 0.0f) continue;                 // whole-row skip
            const uint4* __restrict__ rowp =
                base + min(ybase + yi, HH - 1) * (WW * 32);
            float4 r0 = make_float4(0.f, 0.f, 0.f, 0.f);
            float4 r1 = make_float4(0.f, 0.f, 0.f, 0.f);
            #pragma unroll
            for (int xi = 0; xi < 4; xi++) {
                const float wxv = wx[xi];
                const uint4 v = rowp[xo[xi]];
                const __half2* hp = reinterpret_cast<const __half2*>(&v);
                const float2 f0 = __half22float2(hp[0]);
                const float2 f1 = __half22float2(hp[1]);
                const float2 f2 = __half22float2(hp[2]);
                const float2 f3 = __half22float2(hp[3]);
                r0.x += wxv * f0.x; r0.y += wxv * f0.y;
                r0.z += wxv * f1.x; r0.w += wxv * f1.y;
                r1.x += wxv * f2.x; r1.y += wxv * f2.y;
                r1.z += wxv * f3.x; r1.w += wxv * f3.y;
            }
            acc0.x += wyv * r0.x; acc0.y += wyv * r0.y;
            acc0.z += wyv * r0.z; acc0.w += wyv * r0.w;
            acc1.x += wyv * r1.x; acc1.y += wyv * r1.y;
            acc1.z += wyv * r1.z; acc1.w += wyv * r1.w;
        }
        __syncthreads();   // smem safe to overwrite (prev iter readers done)
        smem.sm4[group * 64 + c8 +  0] = acc0;   // even quads: q = 2*c8
        smem.sm4[group * 64 + c8 + 32] = acc1;   // odd quads:  q = 2*c8+1
        __syncthreads();

        // near-coalesced output writes: out[n][c][ph][pw]
        const float* sm = reinterpret_cast<const float*>(smem.sm4);
        const size_t outbase = (size_t)n * (CH * PP * PP) + (size_t)ph * PP;
        const int pw = tid % 7;
        const int cl = tid / 7;
        #pragma unroll
        for (int k = 0; k < 8; k++) {
            const int c  = cl + 32 * k;
            const int q  = c >> 2;
            const int fi = pw * 256 + ((q & 1) << 7) + ((q >> 1) << 2) + (c & 3);
            out[outbase + (size_t)c * (PP * PP) + pw] = sm[fi];
        }
    }
}

extern "C" void kernel_launch(void* const* d_in, const int* in_sizes, int n_in,
                              void* d_out, int out_size) {
    const float* data   = (const float*)d_in[0];   // [4,256,64,64]
    const float* rois   = (const float*)d_in[1];   // [256,5]
    const float* offset = (const float*)d_in[2];   // [256,2,7,7]
    float* out = (float*)d_out;                    // [256,256,7,7]

    deform_roi_pool_fused<<<GRIDP, 224>>>(data, rois, offset, out);
}

// round 16
// speedup vs baseline: 2.0794x; 2.0794x over previous
#include <cuda_runtime.h>
#include <cuda_fp16.h>
#include <cuda_bf16.h>

// Problem constants (fixed by the reference setup_inputs)
#define BATCH 4
#define CH    256
#define HH    64
#define WW    64
#define NROI  256
#define PP    7        // pooled size == part size
#define SS    4        // samples per bin edge
#define SPATIAL_SCALE 0.125f
#define TRANS_STD     0.1f
#define NBINS (NROI * PP * PP)   // 12544

// 8 MB fp16 NHWC scratch: g_nhwc_h[((b*H + y)*W + x)*C + c]
__device__ __half g_nhwc_h[BATCH * HH * WW * CH];

// Per-bin precomputed geometry: 3 x float4 = 48B per bin.
//   [0] = wx[0..3]
//   [1] = wy[0..3] * inv   (count-normalization pre-folded; 0 if count==0)
//   [2] = int4 (xbase, ybase, b, pad) reinterpreted
__device__ float4 g_bininfo[NBINS * 3];

// ---------------------------------------------------------------------------
// Per-bin separable bilinear weights (device function, one thread per bin).
// ---------------------------------------------------------------------------
__device__ __forceinline__ void compute_bin_info(
    int bin, const float* __restrict__ rois, const float* __restrict__ offset)
{
    const int n  = bin / (PP * PP);
    const int r  = bin % (PP * PP);
    const int ph = r / PP;
    const int pw = r % PP;

    const float* roi = rois + n * 5;
    const int   b      = (int)roi[0];
    const float roi_sw = rintf(roi[1]) * SPATIAL_SCALE - 0.5f;
    const float roi_sh = rintf(roi[2]) * SPATIAL_SCALE - 0.5f;
    const float roi_ew = (rintf(roi[3]) + 1.0f) * SPATIAL_SCALE - 0.5f;
    const float roi_eh = (rintf(roi[4]) + 1.0f) * SPATIAL_SCALE - 0.5f;
    const float roi_w  = fmaxf(roi_ew - roi_sw, 0.1f);
    const float roi_h  = fmaxf(roi_eh - roi_sh, 0.1f);
    const float bin_w  = roi_w / (float)PP;
    const float bin_h  = roi_h / (float)PP;
    const float sub_w  = bin_w / (float)SS;
    const float sub_h  = bin_h / (float)SS;

    const float tx_off = offset[(n * 2 + 0) * (PP * PP) + r] * TRANS_STD;
    const float ty_off = offset[(n * 2 + 1) * (PP * PP) + r] * TRANS_STD;

    const float wstart = (float)pw * bin_w + roi_sw + tx_off * roi_w;
    const float hstart = (float)ph * bin_h + roi_sh + ty_off * roi_h;

    float lwx[4] = {0.f, 0.f, 0.f, 0.f};
    int cw = 0, xb = 0;
    bool xset = false;
    #pragma unroll
    for (int s = 0; s < SS; s++) {
        const float wcoord = wstart + (float)s * sub_w;
        if (wcoord > -0.5f && wcoord < (float)WW - 0.5f) {
            cw++;
            const float wc = fminf(fmaxf(wcoord, 0.0f), (float)(WW - 1));
            const int x0 = (int)floorf(wc);
            if (!xset) { xb = x0; xset = true; }
            const float dx = wc - (float)x0;
            const int o0 = x0 - xb;
            const int o1 = min(x0 + 1, WW - 1) - xb;
            #pragma unroll
            for (int k = 0; k < 4; k++)
                lwx[k] += (o0 == k ? 1.0f - dx : 0.0f) + (o1 == k ? dx : 0.0f);
        }
    }
    float lwy[4] = {0.f, 0.f, 0.f, 0.f};
    int chh = 0, yb = 0;
    bool yset = false;
    #pragma unroll
    for (int s = 0; s < SS; s++) {
        const float hcoord = hstart + (float)s * sub_h;
        if (hcoord > -0.5f && hcoord < (float)HH - 0.5f) {
            chh++;
            const float hc = fminf(fmaxf(hcoord, 0.0f), (float)(HH - 1));
            const int y0 = (int)floorf(hc);
            if (!yset) { yb = y0; yset = true; }
            const float dy = hc - (float)y0;
            const int o0 = y0 - yb;
            const int o1 = min(y0 + 1, HH - 1) - yb;
            #pragma unroll
            for (int k = 0; k < 4; k++)
                lwy[k] += (o0 == k ? 1.0f - dy : 0.0f) + (o1 == k ? dy : 0.0f);
        }
    }

    const int cnt = cw * chh;
    const float inv = (cnt > 0) ? (1.0f / (float)cnt) : 0.0f;
    float4* bi = g_bininfo + bin * 3;
    bi[0] = make_float4(lwx[0], lwx[1], lwx[2], lwx[3]);
    bi[1] = make_float4(lwy[0] * inv, lwy[1] * inv, lwy[2] * inv, lwy[3] * inv);
    int4 ib = make_int4(xb, yb, b, 0);
    bi[2] = *reinterpret_cast<float4*>(&ib);
}

// ---------------------------------------------------------------------------
// Kernel 1: NCHW fp32 -> NHWC fp16 transpose (smem-tiled, half2-packed
// stores) + fused bin-info precompute in the first 49 blocks.
// Grid: (2, 8, 256) = 4096 blocks.  (R13-proven)
// ---------------------------------------------------------------------------
__global__ __launch_bounds__(256) void nchw_to_nhwc_kernel(
    const float* __restrict__ data,
    const float* __restrict__ rois,
    const float* __restrict__ offset)
{
    __shared__ float tile[32][33];
    const int bh = blockIdx.z;
    const int b  = bh / HH;
    const int h  = bh % HH;
    const int c0 = blockIdx.y * 32;
    const int w0 = blockIdx.x * 32;
    const int tx = threadIdx.x;
    const int ty = threadIdx.y;

    float v0 = data[((b * CH + (c0 + ty +  0)) * HH + h) * WW + (w0 + tx)];
    float v1 = data[((b * CH + (c0 + ty +  8)) * HH + h) * WW + (w0 + tx)];
    float v2 = data[((b * CH + (c0 + ty + 16)) * HH + h) * WW + (w0 + tx)];
    float v3 = data[((b * CH + (c0 + ty + 24)) * HH + h) * WW + (w0 + tx)];
    tile[ty +  0][tx] = v0;
    tile[ty +  8][tx] = v1;
    tile[ty + 16][tx] = v2;
    tile[ty + 24][tx] = v3;
    __syncthreads();

    // Packed half2 writes: tile[ci][wi] = data(c0+ci, w0+wi).
    const int idx0 = ty * 32 + tx;          // 0..255
    #pragma unroll
    for (int j = 0; j < 2; j++) {
        const int idx = idx0 + j * 256;     // 0..511
        const int row = idx >> 4;           // w offset 0..31
        const int m   = idx & 15;           // half2 index within 32 channels
        const __half2 v = __floats2half2_rn(tile[2 * m][row], tile[2 * m + 1][row]);
        *reinterpret_cast<__half2*>(
            &g_nhwc_h[((size_t)(b * HH + h) * WW + (w0 + row)) * CH + c0 + 2 * m]) = v;
    }

    // Fused, independent bin-info precompute: first 49 blocks x 256 threads.
    const int fb = (blockIdx.z * gridDim.y + blockIdx.y) * gridDim.x + blockIdx.x;
    if (fb < (NBINS + 255) / 256) {
        const int bin = fb * 256 + idx0;
        if (bin < NBINS) compute_bin_info(bin, rois, offset);
    }
}

// ---------------------------------------------------------------------------
// Kernel 2: gather + FMA. One block = one (roi n, ph) row:
// 7 bins (pw) x 32 threads = 224 threads. fp16 cell = 512B => ONE dense
// LDG.128 per warp per cell; lane c8 owns channels [8*c8, 8*c8+8).
// (224, 5): measured-optimal 56-reg / 5-CTA point.
// NEW: staging layout rotated by `group` so the output-phase LDS banks
// depend on BOTH pw and c -> worst 2-way conflicts instead of ~8-way.
// ---------------------------------------------------------------------------
__global__ __launch_bounds__(224, 5) void deform_roi_pool_kernel(
    float* __restrict__ out)
{
    __shared__ float4 sm4[PP * 64];     // [pw][rotated word]

    const int ph = blockIdx.x;          // 0..6
    const int n  = blockIdx.y;          // 0..255
    const int tid   = threadIdx.x;
    const int group = tid >> 5;         // pw, 0..6
    const int c8    = tid & 31;         // lane: channels 8*c8 .. 8*c8+7

    // ---- broadcast-load this bin's precomputed info (3 x LDG.128) -----------
    const int bin = n * (PP * PP) + ph * PP + group;
    const float4* __restrict__ bip = g_bininfo + bin * 3;
    const float4 fwx = __ldg(bip + 0);
    const float4 fwy = __ldg(bip + 1);     // already includes 1/count
    const float4 fib = __ldg(bip + 2);
    const int4   ib  = *reinterpret_cast<const int4*>(&fib);
    const int xbase = ib.x, ybase = ib.y, b = ib.z;
    const float wx[4] = {fwx.x, fwx.y, fwx.z, fwx.w};
    const float wy[4] = {fwy.x, fwy.y, fwy.z, fwy.w};

    // ---- gather + FMA ------------------------------------------------------
    {
        // cell = 256 ch * 2B = 512B = 32 uint4; lane c8 reads uint4 #c8
        const uint4* __restrict__ base =
            reinterpret_cast<const uint4*>(g_nhwc_h)
            + (size_t)b * (HH * WW * 32) + c8;

        int xo[4];
        #pragma unroll
        for (int xi = 0; xi < 4; xi++)
            xo[xi] = min(xbase + xi, WW - 1) * 32;

        float4 acc0 = make_float4(0.f, 0.f, 0.f, 0.f);   // channels 8c8+0..3
        float4 acc1 = make_float4(0.f, 0.f, 0.f, 0.f);   // channels 8c8+4..7
        #pragma unroll
        for (int yi = 0; yi < 4; yi++) {
            const float wyv = wy[yi];
            if (wyv == 0.0f) continue;       // whole-row skip (saves 4 loads)
            const uint4* __restrict__ rowp =
                base + min(ybase + yi, HH - 1) * (WW * 32);
            float4 r0 = make_float4(0.f, 0.f, 0.f, 0.f);
            float4 r1 = make_float4(0.f, 0.f, 0.f, 0.f);
            #pragma unroll
            for (int xi = 0; xi < 4; xi++) {
                const float wxv = wx[xi];
                const uint4 v = rowp[xo[xi]];
                const __half2* hp = reinterpret_cast<const __half2*>(&v);
                const float2 f0 = __half22float2(hp[0]);
                const float2 f1 = __half22float2(hp[1]);
                const float2 f2 = __half22float2(hp[2]);
                const float2 f3 = __half22float2(hp[3]);
                r0.x += wxv * f0.x; r0.y += wxv * f0.y;
                r0.z += wxv * f1.x; r0.w += wxv * f1.y;
                r1.x += wxv * f2.x; r1.y += wxv * f2.y;
                r1.z += wxv * f3.x; r1.w += wxv * f3.y;
            }
            acc0.x += wyv * r0.x; acc0.y += wyv * r0.y;
            acc0.z += wyv * r0.z; acc0.w += wyv * r0.w;
            acc1.x += wyv * r1.x; acc1.y += wyv * r1.y;
            acc1.z += wyv * r1.z; acc1.w += wyv * r1.w;
        }
        // Rotated staging: lane permutation per warp -> STS stays conflict-free,
        // but read-phase bank index becomes f(c, pw) instead of f(c) only.
        const int rot = (c8 + group) & 31;
        sm4[group * 64 + rot +  0] = acc0;   // channels 8c8+0..3
        sm4[group * 64 + rot + 32] = acc1;   // channels 8c8+4..7
    }
    __syncthreads();

    // ---- near-coalesced output writes: out[n][c][ph][pw] --------------------
    // 224 = 32*7 => pw = tid%7, base channel = tid/7 (one division total).
    // Channel c of warp pw lives at float index:
    //   fi = 4*( pw*64 + ((c>>3 + pw) & 31) + 32*((c>>2)&1) ) + (c&3)
    {
        const float* sm = reinterpret_cast<const float*>(sm4);
        const size_t outbase = (size_t)n * (CH * PP * PP) + (size_t)ph * PP;
        const int pw = tid % 7;
        const int cl = tid / 7;
        #pragma unroll
        for (int k = 0; k < 8; k++) {
            const int c  = cl + 32 * k;
            const int fi = ((pw * 64 + (((c >> 3) + pw) & 31)
                             + (((c >> 2) & 1) << 5)) << 2) + (c & 3);
            out[outbase + (size_t)c * (PP * PP) + pw] = sm[fi];
        }
    }
}

extern "C" void kernel_launch(void* const* d_in, const int* in_sizes, int n_in,
                              void* d_out, int out_size) {
    const float* data   = (const float*)d_in[0];   // [4,256,64,64]
    const float* rois   = (const float*)d_in[1];   // [256,5]
    const float* offset = (const float*)d_in[2];   // [256,2,7,7]
    float* out = (float*)d_out;                    // [256,256,7,7]

    dim3 tb(32, 8);
    dim3 tg(WW / 32, CH / 32, BATCH * HH);
    nchw_to_nhwc_kernel<<<tg, tb>>>(data, rois, offset);

    dim3 pg(PP, NROI);                             // (ph, n)
    deform_roi_pool_kernel<<<pg, 224>>>(out);
}